// round 3
// baseline (speedup 1.0000x reference)
#include <cuda_runtime.h>
#include <math.h>

#define TT 256
#define BB 64
#define HH 512
#define G4 2048
#define MM 16384   // T*B
#define NEGV -10000.0f

// ---------------- scratch (device globals; no allocation allowed) ----------------
__device__ float g_xg[(size_t)2*MM*G4];      // per-dir input gates (+biases), reused by both layers: 256 MB
__device__ float g_hseq0[(size_t)MM*1024];   // layer0 output [t*64+b][hf|hb]   : 64 MB
__device__ float g_hseq1[(size_t)MM*1024];   // layer1 output                    : 64 MB
__device__ float g_h[2*2*BB*HH];             // [parity][dir][b][h] ping-pong
__device__ float g_c[2*BB*HH];               // [dir][b][h]
__device__ float g_feats[MM*4];
__device__ unsigned char g_bp[TT*BB*4];

__device__ __forceinline__ float sigf(float x){ return 1.0f/(1.0f+expf(-x)); }

// ---------------- input-gate GEMM:  xg[d][r][n] = A[r]·W_d[n] + bih[n]+bhh[n] ----------------
// A: GATHER -> embedding[sent], else g_hseq0. Tile 128x64, BK=16, 256 thr, 8x4 micro-tile.
template<bool GATHER>
__global__ void __launch_bounds__(256) xgates_kernel(
    const float* __restrict__ emb, const int* __restrict__ sent,
    const float* __restrict__ Wf, const float* __restrict__ Wb,
    const float* __restrict__ bihf, const float* __restrict__ bhhf,
    const float* __restrict__ bihb, const float* __restrict__ bhhb,
    int K)
{
    __shared__ float As[16][132];
    __shared__ float Bs[16][68];
    const int tid = threadIdx.x;
    const int dir = blockIdx.z;
    const float* W   = dir ? Wb   : Wf;
    const float* bih = dir ? bihb : bihf;
    const float* bhh = dir ? bhhb : bhhf;
    const int m_base = blockIdx.y * 128;
    const int n_base = blockIdx.x * 64;

    const int kg = tid & 3;
    const int mA = tid >> 2;          // 0..63 (row i=0), +64 for i=1
    const int nB = tid >> 2;          // 0..63

    const float* aSrc[2];
    #pragma unroll
    for (int i = 0; i < 2; i++) {
        int row = m_base + mA + i*64;
        if (GATHER) {
            int t = row >> 6, b = row & 63;
            int tok = sent[b*TT + t];
            aSrc[i] = emb + (size_t)tok * 256;
        } else {
            aSrc[i] = g_hseq0 + (size_t)row * 1024;
        }
    }
    const float* wRow = W + (size_t)(n_base + nB) * K;

    const int m0t = (tid >> 4) * 8;
    const int n0t = (tid & 15) * 4;
    float acc[8][4];
    #pragma unroll
    for (int i = 0; i < 8; i++)
        #pragma unroll
        for (int j = 0; j < 4; j++) acc[i][j] = 0.f;

    for (int kt = 0; kt < K; kt += 16) {
        #pragma unroll
        for (int i = 0; i < 2; i++) {
            float4 v = *(const float4*)(aSrc[i] + kt + kg*4);
            int m = mA + i*64;
            As[kg*4+0][m] = v.x; As[kg*4+1][m] = v.y;
            As[kg*4+2][m] = v.z; As[kg*4+3][m] = v.w;
        }
        {
            float4 v = *(const float4*)(wRow + kt + kg*4);
            Bs[kg*4+0][nB] = v.x; Bs[kg*4+1][nB] = v.y;
            Bs[kg*4+2][nB] = v.z; Bs[kg*4+3][nB] = v.w;
        }
        __syncthreads();
        #pragma unroll
        for (int k = 0; k < 16; k++) {
            float4 a0 = *(const float4*)&As[k][m0t];
            float4 a1 = *(const float4*)&As[k][m0t+4];
            float4 bv = *(const float4*)&Bs[k][n0t];
            float am[8] = {a0.x,a0.y,a0.z,a0.w,a1.x,a1.y,a1.z,a1.w};
            float bn[4] = {bv.x,bv.y,bv.z,bv.w};
            #pragma unroll
            for (int i = 0; i < 8; i++)
                #pragma unroll
                for (int j = 0; j < 4; j++) acc[i][j] += am[i]*bn[j];
        }
        __syncthreads();
    }

    float4 bi = *(const float4*)(bih + n_base + n0t);
    float4 bh = *(const float4*)(bhh + n_base + n0t);
    float badd[4] = {bi.x+bh.x, bi.y+bh.y, bi.z+bh.z, bi.w+bh.w};
    #pragma unroll
    for (int i = 0; i < 8; i++) {
        int row = m_base + m0t + i;
        float4 o;
        o.x = acc[i][0]+badd[0]; o.y = acc[i][1]+badd[1];
        o.z = acc[i][2]+badd[2]; o.w = acc[i][3]+badd[3];
        *(float4*)&g_xg[((size_t)dir*MM + row)*G4 + n_base + n0t] = o;
    }
}

// ---------------- state init ----------------
__global__ void init_state(const float* __restrict__ h0, const float* __restrict__ c0, int layer)
{
    int idx = blockIdx.x * blockDim.x + threadIdx.x;
    if (idx >= 2*BB*HH) return;
    g_h[idx] = h0[(size_t)layer*2*BB*HH + idx];   // parity 0 region = [dir][b][h]
    g_c[idx] = c0[(size_t)layer*2*BB*HH + idx];
}

// ---------------- fused recurrent step: gates GEMM + activations + c/h update ----------------
// grid 128 = 2 dirs x 64 hidden-tiles(8 units); block computes 64(batch) x 32 gate-cols
// (cols c = gate*8 + u  <->  global gate col gate*512 + j0 + u), K=512.
__global__ void __launch_bounds__(128) lstm_step_kernel(
    const float* __restrict__ Whhf, const float* __restrict__ Whhb,
    int s, int parity, int layer)
{
    __shared__ float As[16][68];
    __shared__ float Bs[16][36];
    __shared__ float gsum[64][36];
    const int tid = threadIdx.x;
    const int dir = blockIdx.x >> 6;
    const int ht  = blockIdx.x & 63;
    const int j0  = ht * 8;
    const int t   = dir ? (TT-1-s) : s;
    const float* W = dir ? Whhb : Whhf;
    const float* hin  = g_h + ((size_t)parity*2 + dir)*BB*HH;
    float*       hout = g_h + ((size_t)(parity^1)*2 + dir)*BB*HH;
    float*       cptr = g_c + (size_t)dir*BB*HH;
    const float* xgrow_base = g_xg + ((size_t)dir*MM + (size_t)t*BB)*G4;
    float* hseq = layer ? g_hseq1 : g_hseq0;

    const int kg = tid & 3;
    const int mA = tid >> 2;          // 0..31 (+32 for i=1)
    const int nB = tid >> 2;          // 0..31 (col index)
    const int gB = nB >> 3, uB = nB & 7;
    const float* wRow = W + (size_t)(gB*HH + j0 + uB) * HH;

    const int m0t = (tid >> 3) * 4;
    const int n0t = (tid & 7) * 4;
    float acc[4][4];
    #pragma unroll
    for (int i = 0; i < 4; i++)
        #pragma unroll
        for (int j = 0; j < 4; j++) acc[i][j] = 0.f;

    for (int kt = 0; kt < HH; kt += 16) {
        #pragma unroll
        for (int i = 0; i < 2; i++) {
            int m = mA + i*32;        // 0..63
            float4 v = *(const float4*)(hin + (size_t)m*HH + kt + kg*4);
            As[kg*4+0][m] = v.x; As[kg*4+1][m] = v.y;
            As[kg*4+2][m] = v.z; As[kg*4+3][m] = v.w;
        }
        {
            float4 v = *(const float4*)(wRow + kt + kg*4);
            Bs[kg*4+0][nB] = v.x; Bs[kg*4+1][nB] = v.y;
            Bs[kg*4+2][nB] = v.z; Bs[kg*4+3][nB] = v.w;
        }
        __syncthreads();
        #pragma unroll
        for (int k = 0; k < 16; k++) {
            float4 a = *(const float4*)&As[k][m0t];
            float4 b = *(const float4*)&Bs[k][n0t];
            float am[4] = {a.x,a.y,a.z,a.w};
            float bn[4] = {b.x,b.y,b.z,b.w};
            #pragma unroll
            for (int i = 0; i < 4; i++)
                #pragma unroll
                for (int j = 0; j < 4; j++) acc[i][j] += am[i]*bn[j];
        }
        __syncthreads();
    }

    #pragma unroll
    for (int i = 0; i < 4; i++) {
        float4 o = {acc[i][0], acc[i][1], acc[i][2], acc[i][3]};
        *(float4*)&gsum[m0t+i][n0t] = o;
    }
    __syncthreads();

    #pragma unroll
    for (int i = 0; i < 4; i++) {
        int it = tid + i*128;          // 0..511
        int b = it >> 3, u = it & 7;
        const float* xr = xgrow_base + (size_t)b*G4;
        float gi = gsum[b][ 0+u] + xr[0*HH + j0 + u];
        float gf = gsum[b][ 8+u] + xr[1*HH + j0 + u];
        float gg = gsum[b][16+u] + xr[2*HH + j0 + u];
        float go = gsum[b][24+u] + xr[3*HH + j0 + u];
        float cp = cptr[b*HH + j0 + u];
        float cn = sigf(gf)*cp + sigf(gi)*tanhf(gg);
        float hn = sigf(go)*tanhf(cn);
        cptr[b*HH + j0 + u] = cn;
        hout[b*HH + j0 + u] = hn;
        hseq[((size_t)t*BB + b)*1024 + dir*HH + j0 + u] = hn;
    }
}

// ---------------- feats: [16384,4] = hseq1 @ w_out^T + b_out ----------------
__global__ void __launch_bounds__(128) feats_kernel(const float* __restrict__ w_out,
                                                    const float* __restrict__ b_out)
{
    __shared__ float red[128][4];
    int r = blockIdx.x, tid = threadIdx.x;
    const float* x = g_hseq1 + (size_t)r * 1024;
    float a0=0.f, a1=0.f, a2=0.f, a3=0.f;
    for (int k = tid; k < 1024; k += 128) {
        float xv = x[k];
        a0 += xv * w_out[k];
        a1 += xv * w_out[1024 + k];
        a2 += xv * w_out[2048 + k];
        a3 += xv * w_out[3072 + k];
    }
    red[tid][0]=a0; red[tid][1]=a1; red[tid][2]=a2; red[tid][3]=a3;
    __syncthreads();
    for (int off = 64; off > 0; off >>= 1) {
        if (tid < off) {
            red[tid][0]+=red[tid+off][0]; red[tid][1]+=red[tid+off][1];
            red[tid][2]+=red[tid+off][2]; red[tid][3]+=red[tid+off][3];
        }
        __syncthreads();
    }
    if (tid < 4) g_feats[r*4 + tid] = red[0][tid] + b_out[tid];
}

// ---------------- Viterbi (K=4), single block; out = [score(64) | path(64x256)] as f32 ----------------
__global__ void viterbi_kernel(const float* __restrict__ trans, float* __restrict__ out)
{
    __shared__ float fv[64][4];
    __shared__ float tr[4][4];
    int tid = threadIdx.x;
    if (tid < 16) tr[tid>>2][tid&3] = trans[tid];
    int b = tid >> 2, nx = tid & 3;
    fv[b][nx] = (nx == 2) ? 0.0f : NEGV;   // START = 2
    __syncthreads();

    for (int t = 0; t < TT; t++) {
        float best = fv[b][0] + tr[nx][0];
        int arg = 0;
        #pragma unroll
        for (int p = 1; p < 4; p++) {
            float sc = fv[b][p] + tr[nx][p];
            if (sc > best) { best = sc; arg = p; }
        }
        float nf = best + g_feats[((size_t)t*BB + b)*4 + nx];
        g_bp[((size_t)t*BB + b)*4 + nx] = (unsigned char)arg;
        __syncthreads();
        fv[b][nx] = nf;
        __syncthreads();
    }

    if (tid < 64) {
        int bb = tid;
        float best = fv[bb][0] + tr[3][0];   // STOP = 3
        int arg = 0;
        #pragma unroll
        for (int k = 1; k < 4; k++) {
            float sc = fv[bb][k] + tr[3][k];
            if (sc > best) { best = sc; arg = k; }
        }
        out[bb] = best;
        int tag = arg;
        out[64 + bb*TT + (TT-1)] = (float)tag;
        for (int t = TT-2; t >= 0; --t) {
            tag = g_bp[((size_t)(t+1)*BB + bb)*4 + tag];
            out[64 + bb*TT + t] = (float)tag;
        }
    }
}

// ---------------- driver ----------------
extern "C" void kernel_launch(void* const* d_in, const int* in_sizes, int n_in,
                              void* d_out, int out_size)
{
    const int*   sent  = (const int*)  d_in[0];
    const float* emb   = (const float*)d_in[1];
    const float* wih0f = (const float*)d_in[2];
    const float* whh0f = (const float*)d_in[3];
    const float* bih0f = (const float*)d_in[4];
    const float* bhh0f = (const float*)d_in[5];
    const float* wih0b = (const float*)d_in[6];
    const float* whh0b = (const float*)d_in[7];
    const float* bih0b = (const float*)d_in[8];
    const float* bhh0b = (const float*)d_in[9];
    const float* wih1f = (const float*)d_in[10];
    const float* whh1f = (const float*)d_in[11];
    const float* bih1f = (const float*)d_in[12];
    const float* bhh1f = (const float*)d_in[13];
    const float* wih1b = (const float*)d_in[14];
    const float* whh1b = (const float*)d_in[15];
    const float* bih1b = (const float*)d_in[16];
    const float* bhh1b = (const float*)d_in[17];
    const float* h0    = (const float*)d_in[18];
    const float* c0    = (const float*)d_in[19];
    const float* w_out = (const float*)d_in[20];
    const float* b_out = (const float*)d_in[21];
    const float* trans = (const float*)d_in[22];
    float* out = (float*)d_out;

    dim3 gx(32, 128, 2);

    // layer 0
    xgates_kernel<true><<<gx, 256>>>(emb, sent, wih0f, wih0b, bih0f, bhh0f, bih0b, bhh0b, 256);
    init_state<<<(2*BB*HH + 255)/256, 256>>>(h0, c0, 0);
    for (int s = 0; s < TT; s++)
        lstm_step_kernel<<<128, 128>>>(whh0f, whh0b, s, s & 1, 0);

    // layer 1
    xgates_kernel<false><<<gx, 256>>>(emb, sent, wih1f, wih1b, bih1f, bhh1f, bih1b, bhh1b, 1024);
    init_state<<<(2*BB*HH + 255)/256, 256>>>(h0, c0, 1);
    for (int s = 0; s < TT; s++)
        lstm_step_kernel<<<128, 128>>>(whh1f, whh1b, s, s & 1, 1);

    // emissions + decode
    feats_kernel<<<MM, 128>>>(w_out, b_out);
    viterbi_kernel<<<1, 256>>>(trans, out);
}